// round 1
// baseline (speedup 1.0000x reference)
#include <cuda_runtime.h>
#include <cuda_bf16.h>

// ---------------------------------------------------------------------------
// HashEncoder (instant-ngp style), GB300 sm_103a
//   B points (x,y,z in [0,1]) -> [B, 16 levels * 2 feats] fp32
//   All 16 levels use the spatial-hash path (table sizes rounded down to 8).
// ---------------------------------------------------------------------------

#define TP       16          // points per block
#define NLEVELS  16
#define NTHREADS (TP * NLEVELS)

// Per-level table offsets (in float2 entries), exactly the reference formula:
//   res_l = 16 << l ; p = min(2^19, (res_l+1)^3) ; p = (p/8)*8
__constant__ unsigned c_off[NLEVELS] = {
    0u,        4912u,     40848u,    315472u,
    839760u,   1364048u,  1888336u,  2412624u,
    2936912u,  3461200u,  3985488u,  4509776u,
    5034064u,  5558352u,  6082640u,  6606928u
};

__global__ __launch_bounds__(NTHREADS)
void hash_encoder_kernel(const float* __restrict__ xyz,
                         const float2* __restrict__ emb,
                         float2* __restrict__ out,
                         int B)
{
    __shared__ float  sxyz[TP * 3];
    __shared__ float2 sres[TP][NLEVELS + 1];   // +1 pad: kill bank conflicts

    const int tid   = threadIdx.x;
    const int level = tid >> 4;      // 0..15
    const int p     = tid & 15;      // point within block
    const long long base = (long long)blockIdx.x * TP;

    // stage this block's 16 points (48 floats), coalesced
    if (tid < TP * 3) {
        long long g = base * 3 + tid;
        sxyz[tid] = (g < (long long)B * 3) ? xyz[g] : 0.0f;
    }
    __syncthreads();

    const float x = sxyz[p * 3 + 0];
    const float y = sxyz[p * 3 + 1];
    const float z = sxyz[p * 3 + 2];

    // scale = exp2(level)*16 - 1  (exact in fp32)
    const float scale = (float)(16u << level) - 1.0f;

    const float px = fmaf(x, scale, 0.5f);
    const float py = fmaf(y, scale, 0.5f);
    const float pz = fmaf(z, scale, 0.5f);
    const float gx_f = floorf(px), gy_f = floorf(py), gz_f = floorf(pz);
    const float fx = px - gx_f, fy = py - gy_f, fz = pz - gz_f;
    const unsigned gx = (unsigned)gx_f;
    const unsigned gy = (unsigned)gy_f;
    const unsigned gz = (unsigned)gz_f;

    // spatial hash: idx = (x*1) ^ (y*2654435761) ^ (z*805459861)  (u32 wrap)
    const unsigned hx0 = gx;
    const unsigned hx1 = gx + 1u;
    const unsigned hy0 = gy * 2654435761u;
    const unsigned hy1 = (gy + 1u) * 2654435761u;
    const unsigned hz0 = gz * 805459861u;
    const unsigned hz1 = (gz + 1u) * 805459861u;

    unsigned idx[8];
    idx[0] = hx0 ^ hy0 ^ hz0;   // c=0: (0,0,0)
    idx[1] = hx1 ^ hy0 ^ hz0;   // c=1: (1,0,0)
    idx[2] = hx0 ^ hy1 ^ hz0;   // c=2: (0,1,0)
    idx[3] = hx1 ^ hy1 ^ hz0;   // c=3
    idx[4] = hx0 ^ hy0 ^ hz1;   // c=4
    idx[5] = hx1 ^ hy0 ^ hz1;   // c=5
    idx[6] = hx0 ^ hy1 ^ hz1;   // c=6
    idx[7] = hx1 ^ hy1 ^ hz1;   // c=7

    // modulo by per-level table size; constants let ptxas emit magic-mul mod.
    // Warp layout (level = tid>>4) keeps divergence to <=2 ways per warp.
    if (level >= 3) {
        #pragma unroll
        for (int c = 0; c < 8; c++) idx[c] &= 524287u;       // 2^19 mask
    } else if (level == 2) {
        #pragma unroll
        for (int c = 0; c < 8; c++) idx[c] %= 274624u;
    } else if (level == 1) {
        #pragma unroll
        for (int c = 0; c < 8; c++) idx[c] %= 35936u;
    } else {
        #pragma unroll
        for (int c = 0; c < 8; c++) idx[c] %= 4912u;
    }

    // 8 independent gathers (MLP=8): L1 for low levels, L2 for the 4MB tables
    const float2* __restrict__ tab = emb + c_off[level];
    float2 v0 = __ldg(&tab[idx[0]]);
    float2 v1 = __ldg(&tab[idx[1]]);
    float2 v2 = __ldg(&tab[idx[2]]);
    float2 v3 = __ldg(&tab[idx[3]]);
    float2 v4 = __ldg(&tab[idx[4]]);
    float2 v5 = __ldg(&tab[idx[5]]);
    float2 v6 = __ldg(&tab[idx[6]]);
    float2 v7 = __ldg(&tab[idx[7]]);

    const float wx0 = 1.0f - fx, wy0 = 1.0f - fy, wz0 = 1.0f - fz;
    float w0 = (wx0 * wy0) * wz0;
    float w1 = (fx  * wy0) * wz0;
    float w2 = (wx0 * fy ) * wz0;
    float w3 = (fx  * fy ) * wz0;
    float w4 = (wx0 * wy0) * fz;
    float w5 = (fx  * wy0) * fz;
    float w6 = (wx0 * fy ) * fz;
    float w7 = (fx  * fy ) * fz;

    float rx = 0.0f, ry = 0.0f;
    rx = fmaf(w0, v0.x, rx);  ry = fmaf(w0, v0.y, ry);
    rx = fmaf(w1, v1.x, rx);  ry = fmaf(w1, v1.y, ry);
    rx = fmaf(w2, v2.x, rx);  ry = fmaf(w2, v2.y, ry);
    rx = fmaf(w3, v3.x, rx);  ry = fmaf(w3, v3.y, ry);
    rx = fmaf(w4, v4.x, rx);  ry = fmaf(w4, v4.y, ry);
    rx = fmaf(w5, v5.x, rx);  ry = fmaf(w5, v5.y, ry);
    rx = fmaf(w6, v6.x, rx);  ry = fmaf(w6, v6.y, ry);
    rx = fmaf(w7, v7.x, rx);  ry = fmaf(w7, v7.y, ry);

    sres[p][level] = make_float2(rx, ry);
    __syncthreads();

    // coalesced writeback: block's tile is 16 points x 16 float2, contiguous
    const int pp = tid >> 4;     // point for writeback
    const int ll = tid & 15;     // level for writeback
    if (base + pp < (long long)B) {
        out[base * NLEVELS + tid] = sres[pp][ll];   // out[(base+pp)*16 + ll]
    }
}

extern "C" void kernel_launch(void* const* d_in, const int* in_sizes, int n_in,
                              void* d_out, int out_size)
{
    const float*  xyz = (const float*)d_in[0];
    const float2* emb = (const float2*)d_in[1];
    // d_in[2] = normalize flag (0) -> raw coordinates path; ignored.

    const int B = in_sizes[0] / 3;
    const int blocks = (B + TP - 1) / TP;

    hash_encoder_kernel<<<blocks, NTHREADS>>>(xyz, emb, (float2*)d_out, B);
}

// round 2
// speedup vs baseline: 1.0633x; 1.0633x over previous
#include <cuda_runtime.h>
#include <cuda_bf16.h>

// ---------------------------------------------------------------------------
// HashEncoder (instant-ngp style), GB300 sm_103a
//   B points (x,y,z in [0,1]) -> [B, 16 levels * 2 feats] fp32
//   All 16 levels take the spatial-hash path (table sizes rounded down to 8).
//
// R2: for mask-levels (>=3), x-adjacent corner pairs share one aligned
//     float4 when gx is even (idx^1 pairing survives the 2^19 mask):
//     4x LDG.128 instead of 8x LDG.64 -> ~20% fewer L1tex/L2 sector touches.
// ---------------------------------------------------------------------------

#define TP       16          // points per block
#define NLEVELS  16
#define NTHREADS (TP * NLEVELS)

__constant__ unsigned c_off[NLEVELS] = {
    0u,        4912u,     40848u,    315472u,
    839760u,   1364048u,  1888336u,  2412624u,
    2936912u,  3461200u,  3985488u,  4509776u,
    5034064u,  5558352u,  6082640u,  6606928u
};

__global__ __launch_bounds__(NTHREADS)
void hash_encoder_kernel(const float* __restrict__ xyz,
                         const float2* __restrict__ emb,
                         float2* __restrict__ out,
                         int B)
{
    __shared__ float  sxyz[TP * 3];
    __shared__ float2 sres[TP][NLEVELS + 1];   // +1 pad: kill bank conflicts

    const int tid   = threadIdx.x;
    const int level = tid >> 4;      // 0..15
    const int p     = tid & 15;      // point within block
    const long long base = (long long)blockIdx.x * TP;

    // stage this block's 16 points (48 floats), coalesced
    if (tid < TP * 3) {
        long long g = base * 3 + tid;
        sxyz[tid] = (g < (long long)B * 3) ? xyz[g] : 0.0f;
    }
    __syncthreads();

    const float x = sxyz[p * 3 + 0];
    const float y = sxyz[p * 3 + 1];
    const float z = sxyz[p * 3 + 2];

    // scale = exp2(level)*16 - 1  (exact in fp32)
    const float scale = (float)(16u << level) - 1.0f;

    const float px = fmaf(x, scale, 0.5f);
    const float py = fmaf(y, scale, 0.5f);
    const float pz = fmaf(z, scale, 0.5f);
    const float gx_f = floorf(px), gy_f = floorf(py), gz_f = floorf(pz);
    const float fx = px - gx_f, fy = py - gy_f, fz = pz - gz_f;
    const unsigned gx = (unsigned)gx_f;
    const unsigned gy = (unsigned)gy_f;
    const unsigned gz = (unsigned)gz_f;

    // spatial hash: idx = (x*1) ^ (y*2654435761) ^ (z*805459861)  (u32 wrap)
    const unsigned hx0 = gx;
    const unsigned hx1 = gx + 1u;
    const unsigned hy0 = gy * 2654435761u;
    const unsigned hy1 = (gy + 1u) * 2654435761u;
    const unsigned hz0 = gz * 805459861u;
    const unsigned hz1 = (gz + 1u) * 805459861u;

    unsigned idx[8];
    idx[0] = hx0 ^ hy0 ^ hz0;   // corner bit0 = x, bit1 = y, bit2 = z
    idx[1] = hx1 ^ hy0 ^ hz0;
    idx[2] = hx0 ^ hy1 ^ hz0;
    idx[3] = hx1 ^ hy1 ^ hz0;
    idx[4] = hx0 ^ hy0 ^ hz1;
    idx[5] = hx1 ^ hy0 ^ hz1;
    idx[6] = hx0 ^ hy1 ^ hz1;
    idx[7] = hx1 ^ hy1 ^ hz1;

    const float2* __restrict__ tab = emb + c_off[level];
    float2 v[8];

    if (level >= 3) {
        #pragma unroll
        for (int c = 0; c < 8; c++) idx[c] &= 524287u;       // 2^19 mask

        if ((gx & 1u) == 0u) {
            // gx even -> idx[2p+1] == idx[2p]^1: each x-pair is an aligned
            // {2k, 2k+1} entry pair -> one float4 (one 32B sector).
            #pragma unroll
            for (int pr = 0; pr < 4; pr++) {
                const unsigned i0 = idx[2 * pr];
                const unsigned b  = i0 & ~1u;
                const float4 q = __ldg((const float4*)(tab + b));
                const float2 lo = make_float2(q.x, q.y);
                const float2 hi = make_float2(q.z, q.w);
                const bool odd = (i0 & 1u);
                v[2 * pr]     = odd ? hi : lo;
                v[2 * pr + 1] = odd ? lo : hi;
            }
        } else {
            #pragma unroll
            for (int c = 0; c < 8; c++) v[c] = __ldg(&tab[idx[c]]);
        }
    } else {
        // non-power-of-2 tables: magic-mul modulo, separate gathers
        if (level == 2) {
            #pragma unroll
            for (int c = 0; c < 8; c++) idx[c] %= 274624u;
        } else if (level == 1) {
            #pragma unroll
            for (int c = 0; c < 8; c++) idx[c] %= 35936u;
        } else {
            #pragma unroll
            for (int c = 0; c < 8; c++) idx[c] %= 4912u;
        }
        #pragma unroll
        for (int c = 0; c < 8; c++) v[c] = __ldg(&tab[idx[c]]);
    }

    const float wx0 = 1.0f - fx, wy0 = 1.0f - fy, wz0 = 1.0f - fz;
    float w[8];
    w[0] = (wx0 * wy0) * wz0;
    w[1] = (fx  * wy0) * wz0;
    w[2] = (wx0 * fy ) * wz0;
    w[3] = (fx  * fy ) * wz0;
    w[4] = (wx0 * wy0) * fz;
    w[5] = (fx  * wy0) * fz;
    w[6] = (wx0 * fy ) * fz;
    w[7] = (fx  * fy ) * fz;

    float rx = 0.0f, ry = 0.0f;
    #pragma unroll
    for (int c = 0; c < 8; c++) {
        rx = fmaf(w[c], v[c].x, rx);
        ry = fmaf(w[c], v[c].y, ry);
    }

    sres[p][level] = make_float2(rx, ry);
    __syncthreads();

    // coalesced writeback: block tile = 16 points x 16 float2, contiguous
    const int pp = tid >> 4;
    const int ll = tid & 15;
    if (base + pp < (long long)B) {
        out[base * NLEVELS + tid] = sres[pp][ll];
    }
}

extern "C" void kernel_launch(void* const* d_in, const int* in_sizes, int n_in,
                              void* d_out, int out_size)
{
    const float*  xyz = (const float*)d_in[0];
    const float2* emb = (const float2*)d_in[1];
    // d_in[2] = normalize flag (0) -> raw coordinates path; ignored.

    const int B = in_sizes[0] / 3;
    const int blocks = (B + TP - 1) / TP;

    hash_encoder_kernel<<<blocks, NTHREADS>>>(xyz, emb, (float2*)d_out, B);
}